// round 3
// baseline (speedup 1.0000x reference)
#include <cuda_runtime.h>
#include <cstdint>

// BilinearInteraction: out[b, p, :] = x[b, i_p, :] * (x[b, j_p, :] @ W)
//   x: [4096, 32, 64] f32, W: [64, 64] f32, out: [4096, 496, 64] f32
//   pairs (i,j), i<j, row-major triu k=1 ordering.

#define NF 32
#define ED 64
#define NP 496           // NF*(NF-1)/2
#define NTHREADS 256
#define NBATCH 4096

__global__ void __launch_bounds__(NTHREADS, 6)
bilinear_kernel(const float* __restrict__ x,
                const float* __restrict__ W,
                float* __restrict__ out)
{
    __shared__ float xs[NF * ED];      // 8 KB  : x[b] tile
    __shared__ float Ws[ED * ED];      // 16 KB : W
    __shared__ float vs[NF * ED];      // 8 KB  : vid[b] tile

    const int b   = blockIdx.x;
    const int tid = threadIdx.x;

    // ---- Load x[b] (512 float4) and W (1024 float4) into SMEM ----
    {
        const float4* xg  = (const float4*)(x + (size_t)b * (NF * ED));
        float4*       xs4 = (float4*)xs;
        xs4[tid]       = xg[tid];
        xs4[tid + 256] = xg[tid + 256];

        const float4* wg  = (const float4*)W;
        float4*       ws4 = (float4*)Ws;
#pragma unroll
        for (int k = 0; k < 4; k++)
            ws4[tid + k * 256] = wg[tid + k * 256];
    }
    __syncthreads();

    // ---- Compute vid[f][e] = sum_d x[f][d] * W[d][e] ----
    // Thread owns column e = tid & 63 and 8 strided rows f = fb + 4*k.
    {
        const int e  = tid & 63;
        const int fb = tid >> 6;

        float acc[8];
#pragma unroll
        for (int k = 0; k < 8; k++) acc[k] = 0.0f;

        const float4* xs4 = (const float4*)xs;
#pragma unroll
        for (int d4 = 0; d4 < ED; d4 += 4) {
            const float w0 = Ws[(d4 + 0) * ED + e];
            const float w1 = Ws[(d4 + 1) * ED + e];
            const float w2 = Ws[(d4 + 2) * ED + e];
            const float w3 = Ws[(d4 + 3) * ED + e];
#pragma unroll
            for (int k = 0; k < 8; k++) {
                const int f = fb + 4 * k;
                const float4 xv = xs4[f * (ED / 4) + (d4 >> 2)];
                acc[k] = fmaf(xv.x, w0, acc[k]);
                acc[k] = fmaf(xv.y, w1, acc[k]);
                acc[k] = fmaf(xv.z, w2, acc[k]);
                acc[k] = fmaf(xv.w, w3, acc[k]);
            }
        }
#pragma unroll
        for (int k = 0; k < 8; k++)
            vs[(fb + 4 * k) * ED + e] = acc[k];
    }
    __syncthreads();

    // ---- Write phase: 4 i-rows share one j-loop ----
    // Warp w owns rows {w, 15-w, 15+w, 30-w} (64 pairs; warp 0: {0,15,31*,30},
    // row 31 is a sentinel with an empty j-range). x-rows cached in registers.
    // Per iter: 1 LDS.128 (vid[j],vid[j+1], 512B = 4 wf) + up to 4 contiguous
    // STG.128 (pairs (i,j),(i,j+1) adjacent in p).
    {
        const int w    = tid >> 5;
        const int lane = tid & 31;
        const int v    = lane & 15;
        const int h    = lane >> 4;

        float4*       out4 = (float4*)(out + (size_t)b * (NP * ED));
        const float4* xs4  = (const float4*)xs;
        const float4* vs4  = (const float4*)vs;

        const int r0 = w;
        const int r1 = 15 - w;
        const int r2 = (w == 0) ? 31 : 15 + w;   // sentinel for w==0 (no stores)
        const int r3 = 30 - w;

        const float4 a0 = xs4[r0 * (ED / 4) + v];
        const float4 a1 = xs4[r1 * (ED / 4) + v];
        const float4 a2 = xs4[r2 * (ED / 4) + v];
        const float4 a3 = xs4[r3 * (ED / 4) + v];

        const int p0 = (r0 * (63 - r0)) >> 1;    // row start offsets in p
        const int p1 = (r1 * (63 - r1)) >> 1;
        const int p2 = (r2 * (63 - r2)) >> 1;
        const int p3 = (r3 * (63 - r3)) >> 1;

        const int jbase = w + 1;                  // min row is r0 = w
        const int iters = (32 - w) >> 1;          // ceil((31-w)/2)

#pragma unroll 4
        for (int t = 0; t < iters; t++) {
            const int j = jbase + 2 * t + h;
            if (j <= 31) {
                const float4 c = vs4[j * (ED / 4) + v];
                if (j > r0) {
                    float4 r; r.x = a0.x * c.x; r.y = a0.y * c.y;
                              r.z = a0.z * c.z; r.w = a0.w * c.w;
                    out4[(p0 + j - r0 - 1) * (ED / 4) + v] = r;
                }
                if (j > r1) {
                    float4 r; r.x = a1.x * c.x; r.y = a1.y * c.y;
                              r.z = a1.z * c.z; r.w = a1.w * c.w;
                    out4[(p1 + j - r1 - 1) * (ED / 4) + v] = r;
                }
                if (j > r2) {
                    float4 r; r.x = a2.x * c.x; r.y = a2.y * c.y;
                              r.z = a2.z * c.z; r.w = a2.w * c.w;
                    out4[(p2 + j - r2 - 1) * (ED / 4) + v] = r;
                }
                if (j > r3) {
                    float4 r; r.x = a3.x * c.x; r.y = a3.y * c.y;
                              r.z = a3.z * c.z; r.w = a3.w * c.w;
                    out4[(p3 + j - r3 - 1) * (ED / 4) + v] = r;
                }
            }
        }
    }
}

extern "C" void kernel_launch(void* const* d_in, const int* in_sizes, int n_in,
                              void* d_out, int out_size)
{
    const float* x = (const float*)d_in[0];
    const float* W = (const float*)d_in[1];
    float*       o = (float*)d_out;
    bilinear_kernel<<<NBATCH, NTHREADS>>>(x, W, o);
}